// round 1
// baseline (speedup 1.0000x reference)
#include <cuda_runtime.h>
#include <cuda_bf16.h>

// SSIM fused kernel: 5 separable 11x11 Gaussian convs + SSIM map + mean,
// all in one streaming pass. fp32 throughout.

#define IMG_W 512
#define IMG_H 512
#define NPLANES 48           // 16 batch * 3 channels
#define PLANE_STRIDE (512*512)
#define BW 128               // output strip width  (threads per CTA)
#define BH 128               // output strip height
#define LOAD_W 138           // BW + 10 halo columns
#define STEPS 143            // 13 * 11 (>= BH + 10, multiple of 11)
#define NBLOCKS 768          // 48 * 4 * 4
#define C1_CONST 0.0001f     // 0.01^2
#define C2_CONST 0.0009f     // 0.03^2

// Gaussian window, sigma=1.5, 11 taps, normalized (matches reference fp32 weights).
static __device__ __constant__ const float GWc[11] = {0}; // unused placeholder (weights are immediates)

#define GW0 0.00102838f
#define GW1 0.00759876f
#define GW2 0.03600077f
#define GW3 0.10936080f
#define GW4 0.21300555f
#define GW5 0.26601174f

__device__ __forceinline__ float gwt(int k) {
    // compile-time folded when k is a constant (all call sites are fully unrolled)
    switch (k) {
        case 0: case 10: return GW0;
        case 1: case 9:  return GW1;
        case 2: case 8:  return GW2;
        case 3: case 7:  return GW3;
        case 4: case 6:  return GW4;
        default:         return GW5;
    }
}

__device__ float g_partial[NBLOCKS];

__global__ void __launch_bounds__(BW)
ssim_main_kernel(const float* __restrict__ img1, const float* __restrict__ img2) {
    __shared__ float s1[2][144];
    __shared__ float s2[2][144];
    __shared__ float wsum[4];

    const int t  = threadIdx.x;
    const int b  = blockIdx.x;
    const int plane = b >> 4;          // 0..47
    const int xs = b & 3;
    const int ys = (b >> 2) & 3;
    const int x0 = xs * BW;
    const int y0 = ys * BH;

    const float* p1 = img1 + (size_t)plane * PLANE_STRIDE;
    const float* p2 = img2 + (size_t)plane * PLANE_STRIDE;

    // vertical scatter ring: acc[j] completes j steps from "now"; 5 quantities each
    float acc[11][5];
#pragma unroll
    for (int j = 0; j < 11; ++j)
#pragma unroll
        for (int q = 0; q < 5; ++q) acc[j][q] = 0.f;

    float lsum = 0.f;

    // row loader: step -> input row (y0 - 5 + step); zero outside image / past useful rows
    auto load_row = [&](int step, int buf) {
        const int r   = y0 - 5 + step;
        const bool rok = (r >= 0) && (r < IMG_H) && (step < BH + 10);
        const float* q1 = p1 + (size_t)(rok ? r : 0) * IMG_W;
        const float* q2 = p2 + (size_t)(rok ? r : 0) * IMG_W;
        {
            const int xg  = x0 - 5 + t;
            const bool ok = rok && (xg >= 0) && (xg < IMG_W);
            s1[buf][t] = ok ? q1[xg] : 0.f;
            s2[buf][t] = ok ? q2[xg] : 0.f;
        }
        if (t < LOAD_W - BW) {                 // 10 halo columns
            const int i   = t + BW;
            const int xg  = x0 - 5 + i;        // >= 123, never negative
            const bool ok = rok && (xg < IMG_W);
            s1[buf][i] = ok ? q1[xg] : 0.f;
            s2[buf][i] = ok ? q2[xg] : 0.f;
        }
    };

    load_row(0, 0);

    for (int rb = 0; rb < STEPS; rb += 11) {
#pragma unroll
        for (int rr = 0; rr < 11; ++rr) {
            const int s   = rb + rr;
            __syncthreads();
            const int cur = s & 1;
            // prefetch next row into the other buffer
            load_row(s + 1, cur ^ 1);

            // horizontal 11-tap conv of (i1, i2, i1^2, i2^2, i1*i2)
            const float* r1 = s1[cur];
            const float* r2 = s2[cur];
            float h0 = 0.f, h1 = 0.f, h2 = 0.f, h3 = 0.f, h4 = 0.f;
#pragma unroll
            for (int k = 0; k < 11; ++k) {
                const float w = gwt(k);
                const float a = r1[t + k];
                const float c = r2[t + k];
                h0 = fmaf(a,     w, h0);
                h1 = fmaf(c,     w, h1);
                h2 = fmaf(a * a, w, h2);
                h3 = fmaf(c * c, w, h3);
                h4 = fmaf(a * c, w, h4);
            }

            // vertical scatter into the register ring (all indices compile-time)
#pragma unroll
            for (int j = 0; j < 11; ++j) {
                const float w = gwt(j);
                const int slot = (rr + j) % 11;
                acc[slot][0] = fmaf(h0, w, acc[slot][0]);
                acc[slot][1] = fmaf(h1, w, acc[slot][1]);
                acc[slot][2] = fmaf(h2, w, acc[slot][2]);
                acc[slot][3] = fmaf(h3, w, acc[slot][3]);
                acc[slot][4] = fmaf(h4, w, acc[slot][4]);
            }

            // slot rr completed output row y = y0 + s - 10
            if (s >= 10 && s < BH + 10) {
                const float mu1 = acc[rr][0], mu2 = acc[rr][1];
                const float e11 = acc[rr][2], e22 = acc[rr][3], e12 = acc[rr][4];
                const float m11 = mu1 * mu1;
                const float m22 = mu2 * mu2;
                const float m12 = mu1 * mu2;
                const float sg1  = e11 - m11;
                const float sg2  = e22 - m22;
                const float sg12 = e12 - m12;
                const float num = (2.f * m12 + C1_CONST) * (2.f * sg12 + C2_CONST);
                const float den = (m11 + m22 + C1_CONST) * (sg1 + sg2 + C2_CONST);
                lsum += __fdividef(num, den);
            }
            // recycle slot rr for the row completing 10 steps from now
#pragma unroll
            for (int q = 0; q < 5; ++q) acc[rr][q] = 0.f;
        }
    }

    // block reduction -> deterministic per-block partial
    float v = lsum;
#pragma unroll
    for (int o = 16; o; o >>= 1) v += __shfl_xor_sync(0xffffffffu, v, o);
    if ((t & 31) == 0) wsum[t >> 5] = v;
    __syncthreads();
    if (t == 0) g_partial[b] = wsum[0] + wsum[1] + wsum[2] + wsum[3];
}

__global__ void ssim_reduce_kernel(float* __restrict__ out) {
    __shared__ float sm[256];
    const int t = threadIdx.x;
    float s = 0.f;
    for (int i = t; i < NBLOCKS; i += 256) s += g_partial[i];
    sm[t] = s;
    __syncthreads();
    for (int o = 128; o > 0; o >>= 1) {
        if (t < o) sm[t] += sm[t + o];
        __syncthreads();
    }
    if (t == 0) out[0] = sm[0] * (1.0f / 12582912.0f);
}

extern "C" void kernel_launch(void* const* d_in, const int* in_sizes, int n_in,
                              void* d_out, int out_size) {
    const float* img1 = (const float*)d_in[0];
    const float* img2 = (const float*)d_in[1];
    (void)in_sizes; (void)n_in; (void)out_size;
    ssim_main_kernel<<<NBLOCKS, BW>>>(img1, img2);
    ssim_reduce_kernel<<<1, 256>>>((float*)d_out);
}